// round 1
// baseline (speedup 1.0000x reference)
#include <cuda_runtime.h>
#include <cstdint>

#define M_BATCH 8192
#define N_OUT   4096
#define K_IN    4096

// Scratch (device globals: allocation-free per harness rules)
__device__ float g_W[(size_t)N_OUT * K_IN];   // tf32-rounded sampled weights, row-major (n, k)
__device__ float g_bias[N_OUT];               // sampled bias column (fp32, added in epilogue)
__device__ float g_klpart[N_OUT];             // per-row KL partial sums

__device__ __forceinline__ uint32_t f2tf32(float f) {
    uint32_t u;
    asm("cvt.rna.tf32.f32 %0, %1;" : "=r"(u) : "f"(f));
    return u;
}

// ---------------------------------------------------------------------------
// Prep: W = q_mu + exp(q_ls)*eps  (tf32-rounded into g_W, bias col -> g_bias)
//       KL partial per output row -> g_klpart
// ---------------------------------------------------------------------------
__global__ void prep_kernel(const float* __restrict__ qmu,
                            const float* __restrict__ qls,
                            const float* __restrict__ pmu,
                            const float* __restrict__ eps,
                            const float* __restrict__ pls_ptr) {
    const int n = blockIdx.x;
    const size_t base = (size_t)n * (K_IN + 1);
    const float pls = *pls_ptr;
    const float inv2ps2 = 0.5f * __expf(-2.0f * pls);   // 1 / (2 * p_sigma^2)
    float local = 0.f;
    for (int k = threadIdx.x; k <= K_IN; k += 256) {
        float qm = qmu[base + k];
        float ql = qls[base + k];
        float pm = pmu[base + k];
        float e  = eps[base + k];
        float qs = __expf(ql);
        float w  = qm + qs * e;
        if (k < K_IN) g_W[(size_t)n * K_IN + k] = __uint_as_float(f2tf32(w));
        else          g_bias[n] = w;
        float d = pm - qm;
        local += (pls - ql) + (qs * qs + d * d) * inv2ps2 - 0.5f;
    }
    __shared__ float red[256];
    red[threadIdx.x] = local;
    __syncthreads();
    #pragma unroll
    for (int s = 128; s > 0; s >>= 1) {
        if (threadIdx.x < s) red[threadIdx.x] += red[threadIdx.x + s];
        __syncthreads();
    }
    if (threadIdx.x == 0) g_klpart[n] = red[0];
}

__global__ void kl_reduce_kernel(float* __restrict__ out, long long idx) {
    float local = 0.f;
    for (int i = threadIdx.x; i < N_OUT; i += 256) local += g_klpart[i];
    __shared__ float red[256];
    red[threadIdx.x] = local;
    __syncthreads();
    #pragma unroll
    for (int s = 128; s > 0; s >>= 1) {
        if (threadIdx.x < s) red[threadIdx.x] += red[threadIdx.x + s];
        __syncthreads();
    }
    if (threadIdx.x == 0) out[idx] = red[0];
}

// ---------------------------------------------------------------------------
// GEMM: out[m][n] = sum_k X[m][k] * W[n][k] + bias[n]
// tf32 mma.sync m16n8k8, 128x128x32 block tile, double-buffered cp.async
// 8 warps: 2 (M) x 4 (N), each warp 64x32 -> 4x4 fragments
// ---------------------------------------------------------------------------
#define BM 128
#define BN 128
#define BK 32
#define SLD 36                       // smem row stride (floats): frag bank = 4*ly+lx, conflict-free
#define STAGE (2 * 128 * SLD)        // floats per pipeline stage (A tile + B tile) = 9216

__device__ __forceinline__ void cp_async16(float* dst, const float* src) {
    uint32_t s = (uint32_t)__cvta_generic_to_shared(dst);
    asm volatile("cp.async.cg.shared.global [%0], [%1], 16;\n" :: "r"(s), "l"(src));
}

__global__ __launch_bounds__(256) void gemm_kernel(const float* __restrict__ X,
                                                   float* __restrict__ out) {
    extern __shared__ float smem[];
    const int tid = threadIdx.x;

    // GROUP_M=8 swizzle for L2 reuse: grid_m=64, grid_n=32
    int pid = blockIdx.x;
    int group = pid >> 8;            // / (8*32)
    int rem = pid & 255;
    const int blockM = ((group << 3) + (rem & 7)) * BM;
    const int blockN = (rem >> 3) * BN;

    // cp.async loader mapping: 256 threads, each does 4 rows x 16B
    const int ldr = tid >> 3;        // 0..31
    const int ldq = tid & 7;         // 0..7 (float4 column group)
    const float* gA = X   + (size_t)(blockM + ldr) * K_IN + ldq * 4;
    const float* gB = g_W + (size_t)(blockN + ldr) * K_IN + ldq * 4;

    const int lane = tid & 31;
    const int warp = tid >> 5;
    const int mBase = (warp & 1) * 64;   // 2 M-warps
    const int nBase = (warp >> 1) * 32;  // 4 N-warps
    const int ly = lane >> 2;
    const int lx = lane & 3;

    float acc[4][4][4];
    #pragma unroll
    for (int i = 0; i < 4; i++)
        #pragma unroll
        for (int j = 0; j < 4; j++)
            #pragma unroll
            for (int r = 0; r < 4; r++) acc[i][j][r] = 0.f;

    const int KT = K_IN / BK;        // 128 k-tiles

    // Prologue: tile 0 into stage 0
    {
        float* sA = smem;
        float* sB = smem + 128 * SLD;
        #pragma unroll
        for (int i = 0; i < 4; i++) {
            cp_async16(sA + (ldr + i * 32) * SLD + ldq * 4, gA + (size_t)(i * 32) * K_IN);
            cp_async16(sB + (ldr + i * 32) * SLD + ldq * 4, gB + (size_t)(i * 32) * K_IN);
        }
        asm volatile("cp.async.commit_group;\n");
    }

    for (int t = 0; t < KT; t++) {
        if (t + 1 < KT) {
            const int st = (t + 1) & 1;
            float* sA = smem + st * STAGE;
            float* sB = sA + 128 * SLD;
            const float* ga = gA + (size_t)(t + 1) * BK;
            const float* gb = gB + (size_t)(t + 1) * BK;
            #pragma unroll
            for (int i = 0; i < 4; i++) {
                cp_async16(sA + (ldr + i * 32) * SLD + ldq * 4, ga + (size_t)(i * 32) * K_IN);
                cp_async16(sB + (ldr + i * 32) * SLD + ldq * 4, gb + (size_t)(i * 32) * K_IN);
            }
            asm volatile("cp.async.commit_group;\n");
            asm volatile("cp.async.wait_group 1;\n");
        } else {
            asm volatile("cp.async.wait_group 0;\n");
        }
        __syncthreads();

        const float* sA = smem + (t & 1) * STAGE;
        const float* sB = sA + 128 * SLD;

        #pragma unroll
        for (int kk = 0; kk < BK; kk += 8) {
            uint32_t af[4][4];
            uint32_t bf[4][2];
            #pragma unroll
            for (int i = 0; i < 4; i++) {
                const float* p = sA + (mBase + i * 16 + ly) * SLD + kk + lx;
                af[i][0] = f2tf32(p[0]);
                af[i][1] = f2tf32(p[8 * SLD]);
                af[i][2] = f2tf32(p[4]);
                af[i][3] = f2tf32(p[8 * SLD + 4]);
            }
            #pragma unroll
            for (int j = 0; j < 4; j++) {
                const float* p = sB + (nBase + j * 8 + ly) * SLD + kk + lx;
                bf[j][0] = __float_as_uint(p[0]);   // pre-rounded to tf32 in prep
                bf[j][1] = __float_as_uint(p[4]);
            }
            #pragma unroll
            for (int i = 0; i < 4; i++)
                #pragma unroll
                for (int j = 0; j < 4; j++) {
                    asm volatile(
                        "mma.sync.aligned.m16n8k8.row.col.f32.tf32.tf32.f32 "
                        "{%0,%1,%2,%3}, {%4,%5,%6,%7}, {%8,%9}, {%0,%1,%2,%3};\n"
                        : "+f"(acc[i][j][0]), "+f"(acc[i][j][1]),
                          "+f"(acc[i][j][2]), "+f"(acc[i][j][3])
                        : "r"(af[i][0]), "r"(af[i][1]), "r"(af[i][2]), "r"(af[i][3]),
                          "r"(bf[j][0]), "r"(bf[j][1]));
                }
        }
        __syncthreads();
    }

    // Epilogue: add sampled bias (the "ones" column of x_aug), fp32 store
    #pragma unroll
    for (int i = 0; i < 4; i++) {
        const int row0 = blockM + mBase + i * 16 + ly;
        #pragma unroll
        for (int j = 0; j < 4; j++) {
            const int col = blockN + nBase + j * 8 + lx * 2;
            float2 gb = *(const float2*)&g_bias[col];
            float2 v0 = make_float2(acc[i][j][0] + gb.x, acc[i][j][1] + gb.y);
            float2 v1 = make_float2(acc[i][j][2] + gb.x, acc[i][j][3] + gb.y);
            *(float2*)&out[(size_t)row0 * N_OUT + col] = v0;
            *(float2*)&out[(size_t)(row0 + 8) * N_OUT + col] = v1;
        }
    }
}

// ---------------------------------------------------------------------------
extern "C" void kernel_launch(void* const* d_in, const int* in_sizes, int n_in,
                              void* d_out, int out_size) {
    const float* x   = (const float*)d_in[0];
    const float* pls = (const float*)d_in[1];
    const float* qmu = (const float*)d_in[2];
    const float* qls = (const float*)d_in[3];
    const float* pmu = (const float*)d_in[4];
    const float* eps = (const float*)d_in[5];
    float* out = (float*)d_out;

    prep_kernel<<<N_OUT, 256>>>(qmu, qls, pmu, eps, pls);
    kl_reduce_kernel<<<1, 256>>>(out, (long long)out_size - 1);

    cudaFuncSetAttribute(gemm_kernel, cudaFuncAttributeMaxDynamicSharedMemorySize,
                         (int)(2 * STAGE * sizeof(float)));
    gemm_kernel<<<(M_BATCH / BM) * (N_OUT / BN), 256, 2 * STAGE * sizeof(float)>>>(x, out);
}

// round 3
// speedup vs baseline: 1.2516x; 1.2516x over previous
#include <cuda_runtime.h>
#include <cstdint>

#define M_BATCH 8192
#define N_OUT   4096
#define K_IN    4096

// Scratch (device globals: allocation-free per harness rules)
__device__ float g_W[(size_t)N_OUT * K_IN];   // tf32-rounded sampled weights, row-major (n,k)
__device__ float g_bias[N_OUT];               // sampled bias column
__device__ float g_klpart[1024];              // per-block KL partials

__device__ __forceinline__ uint32_t f2tf32(float f) {
    uint32_t u;
    asm("cvt.rna.tf32.f32 %0, %1;" : "=r"(u) : "f"(f));
    return u;
}

// ---------------------------------------------------------------------------
// Prep: W = q_mu + exp(q_ls)*eps -> g_W (tf32-rounded) / g_bias, KL partials
// ---------------------------------------------------------------------------
__global__ __launch_bounds__(256) void prep_kernel(const float* __restrict__ qmu,
                                                   const float* __restrict__ qls,
                                                   const float* __restrict__ pmu,
                                                   const float* __restrict__ eps,
                                                   const float* __restrict__ plsp) {
    const float pls  = *plsp;
    const float inv2 = 0.5f * __expf(-2.0f * pls);
    float kl = 0.f;
    const int NT4 = (N_OUT * (K_IN + 1)) >> 2;
    for (int i4 = blockIdx.x * 256 + threadIdx.x; i4 < NT4; i4 += 1024 * 256) {
        float4 qm = ((const float4*)qmu)[i4];
        float4 ql = ((const float4*)qls)[i4];
        float4 pm = ((const float4*)pmu)[i4];
        float4 ep = ((const float4*)eps)[i4];
        #pragma unroll
        for (int j = 0; j < 4; j++) {
            float qmj = (&qm.x)[j], qlj = (&ql.x)[j];
            float pmj = (&pm.x)[j], epj = (&ep.x)[j];
            float qs = __expf(qlj);
            float w  = fmaf(qs, epj, qmj);
            int e = i4 * 4 + j;
            int n = e / 4097;
            int k = e - n * 4097;
            if (k < K_IN) g_W[(size_t)n * K_IN + k] = __uint_as_float(f2tf32(w));
            else          g_bias[n] = w;
            float d = pmj - qmj;
            kl += (pls - qlj) + fmaf(qs, qs, d * d) * inv2 - 0.5f;
        }
    }
    __shared__ float red[256];
    red[threadIdx.x] = kl;
    __syncthreads();
    #pragma unroll
    for (int s = 128; s > 0; s >>= 1) {
        if (threadIdx.x < s) red[threadIdx.x] += red[threadIdx.x + s];
        __syncthreads();
    }
    if (threadIdx.x == 0) g_klpart[blockIdx.x] = red[0];
}

__global__ void kl_reduce_kernel(float* __restrict__ out, long long idx) {
    float local = 0.f;
    for (int i = threadIdx.x; i < 1024; i += 256) local += g_klpart[i];
    __shared__ float red[256];
    red[threadIdx.x] = local;
    __syncthreads();
    #pragma unroll
    for (int s = 128; s > 0; s >>= 1) {
        if (threadIdx.x < s) red[threadIdx.x] += red[threadIdx.x + s];
        __syncthreads();
    }
    if (threadIdx.x == 0) out[idx] = red[0];
}

// ---------------------------------------------------------------------------
// tf32 mma.sync GEMM: out[m][n] = sum_k X[m][k]*W[n][k] + bias[n]
// CTA 128x256x32, 8 warps (2Mx4N), warp tile 64x64.
// ldmatrix.x4.b16 fragment loads on XOR-swizzled 128B rows.
// 4-stage cp.async pipeline.
// ---------------------------------------------------------------------------
#define BM 128
#define BN 256
#define BK 32                          // floats = 128 bytes per row
#define NSTAGE 4
#define A_BYTES (BM * 128)             // 16384
#define STG_BYTES ((BM + BN) * 128)    // 49152
#define SMEM_TOTAL (NSTAGE * STG_BYTES)

__device__ __forceinline__ void cpa16(uint32_t daddr, const float* src) {
    asm volatile("cp.async.cg.shared.global [%0], [%1], 16;" :: "r"(daddr), "l"(src));
}

__device__ __forceinline__ void ldsm4(uint32_t* r, uint32_t addr) {
    asm volatile("ldmatrix.sync.aligned.m8n8.x4.shared.b16 {%0,%1,%2,%3}, [%4];"
                 : "=r"(r[0]), "=r"(r[1]), "=r"(r[2]), "=r"(r[3]) : "r"(addr));
}

__device__ __forceinline__ void mma8(float* c, const uint32_t* a, uint32_t b0, uint32_t b1) {
    asm volatile(
        "mma.sync.aligned.m16n8k8.row.col.f32.tf32.tf32.f32 "
        "{%0,%1,%2,%3}, {%4,%5,%6,%7}, {%8,%9}, {%0,%1,%2,%3};\n"
        : "+f"(c[0]), "+f"(c[1]), "+f"(c[2]), "+f"(c[3])
        : "r"(a[0]), "r"(a[1]), "r"(a[2]), "r"(a[3]), "r"(b0), "r"(b1));
}

__global__ __launch_bounds__(256, 1) void gemm_kernel(const float* __restrict__ X,
                                                      float* __restrict__ out) {
    extern __shared__ char smem[];
    uint32_t sbase;
    asm("{ .reg .u64 t; cvta.to.shared.u64 t, %1; cvt.u32.u64 %0, t; }"
        : "=r"(sbase) : "l"(smem));
    const int tid  = threadIdx.x;
    const int wid  = tid >> 5;
    const int lane = tid & 31;

    // GROUP_M=8 schedule: 64 M-tiles x 16 N-tiles
    const int pid   = blockIdx.x;
    const int group = pid >> 7;
    const int rem   = pid & 127;
    const int blockM = ((group << 3) + (rem & 7)) * BM;
    const int blockN = (rem >> 3) * BN;

    // ---- loader mapping: q = 16B chunk col, rows strided by 32 ----
    const int q  = tid & 7;
    const int r0 = tid >> 3;                          // 0..31
    const float* gA = X   + (size_t)(blockM + r0) * K_IN + q * 4;
    const float* gB = g_W + (size_t)(blockN + r0) * K_IN + q * 4;
    const uint32_t soA = r0 * 128 + ((q ^ (r0 & 7)) << 4);
    const uint32_t soB = A_BYTES + soA;

    // ---- fragment geometry ----
    const int mBase = (wid & 1) * 64;                 // 2 M-warps
    const int nBase = (wid >> 1) * 64;                // 4 N-warps
    const uint32_t rl = lane & 7;
    const uint32_t aKbAdd = (lane >> 4) & 1;          // A: matrices 2,3 -> kb+1
    const uint32_t bKbAdd = (lane >> 3) & 1;          // B: matrices 1,3 -> kb+1
    uint32_t aRowOff[4], bRowOff[4];
    #pragma unroll
    for (int i = 0; i < 4; i++)
        aRowOff[i] = (mBase + i * 16 + (lane & 7) + 8 * ((lane >> 3) & 1)) * 128;
    #pragma unroll
    for (int j2 = 0; j2 < 4; j2++)
        bRowOff[j2] = A_BYTES + (nBase + j2 * 16 + (lane & 7) + 8 * ((lane >> 4) & 1)) * 128;

    float acc[4][8][4];
    #pragma unroll
    for (int i = 0; i < 4; i++)
        #pragma unroll
        for (int j = 0; j < 8; j++)
            #pragma unroll
            for (int r = 0; r < 4; r++) acc[i][j][r] = 0.f;

    const int KT = K_IN / BK;                          // 128

    // prologue: stages 0..2
    #pragma unroll
    for (int t = 0; t < 3; t++) {
        uint32_t base = sbase + t * STG_BYTES;
        #pragma unroll
        for (int i = 0; i < 4; i++) cpa16(base + soA + i * 4096, gA + (size_t)t * BK + (size_t)i * 32 * K_IN);
        #pragma unroll
        for (int i = 0; i < 8; i++) cpa16(base + soB + i * 4096, gB + (size_t)t * BK + (size_t)i * 32 * K_IN);
        asm volatile("cp.async.commit_group;");
    }

    for (int t = 0; t < KT; t++) {
        asm volatile("cp.async.wait_group 2;");
        __syncthreads();

        if (t + 3 < KT) {
            uint32_t base = sbase + ((t + 3) & 3) * STG_BYTES;
            const float* ga = gA + (size_t)(t + 3) * BK;
            const float* gb = gB + (size_t)(t + 3) * BK;
            #pragma unroll
            for (int i = 0; i < 4; i++) cpa16(base + soA + i * 4096, ga + (size_t)i * 32 * K_IN);
            #pragma unroll
            for (int i = 0; i < 8; i++) cpa16(base + soB + i * 4096, gb + (size_t)i * 32 * K_IN);
        }
        asm volatile("cp.async.commit_group;");

        const uint32_t stage = sbase + (t & 3) * STG_BYTES;
        #pragma unroll
        for (int kbi = 0; kbi < 8; kbi += 2) {         // kk = kbi*4
            const uint32_t aXor = ((kbi + aKbAdd) ^ rl) << 4;
            const uint32_t bXor = ((kbi + bKbAdd) ^ rl) << 4;
            uint32_t af[4][4], bq[4][4];
            #pragma unroll
            for (int i = 0; i < 4; i++) ldsm4(af[i], stage + aRowOff[i] + aXor);
            #pragma unroll
            for (int j2 = 0; j2 < 4; j2++) ldsm4(bq[j2], stage + bRowOff[j2] + bXor);
            #pragma unroll
            for (int i = 0; i < 4; i++)
                #pragma unroll
                for (int j2 = 0; j2 < 4; j2++) {
                    mma8(acc[i][2 * j2],     af[i], bq[j2][0], bq[j2][1]);
                    mma8(acc[i][2 * j2 + 1], af[i], bq[j2][2], bq[j2][3]);
                }
        }
    }

    // ---- epilogue: bias add + fp32 stores ----
    const int ly = lane >> 2, lx = lane & 3;
    float2 bias2[8];
    #pragma unroll
    for (int j = 0; j < 8; j++)
        bias2[j] = *(const float2*)&g_bias[blockN + nBase + j * 8 + lx * 2];
    #pragma unroll
    for (int i = 0; i < 4; i++) {
        const int row0 = blockM + mBase + i * 16 + ly;
        #pragma unroll
        for (int j = 0; j < 8; j++) {
            const int col = blockN + nBase + j * 8 + lx * 2;
            float2 v0 = make_float2(acc[i][j][0] + bias2[j].x, acc[i][j][1] + bias2[j].y);
            float2 v1 = make_float2(acc[i][j][2] + bias2[j].x, acc[i][j][3] + bias2[j].y);
            *(float2*)&out[(size_t)row0 * N_OUT + col] = v0;
            *(float2*)&out[(size_t)(row0 + 8) * N_OUT + col] = v1;
        }
    }
}

// ---------------------------------------------------------------------------
extern "C" void kernel_launch(void* const* d_in, const int* in_sizes, int n_in,
                              void* d_out, int out_size) {
    const float* x   = (const float*)d_in[0];
    const float* pls = (const float*)d_in[1];
    const float* qmu = (const float*)d_in[2];
    const float* qls = (const float*)d_in[3];
    const float* pmu = (const float*)d_in[4];
    const float* eps = (const float*)d_in[5];
    float* out = (float*)d_out;

    prep_kernel<<<1024, 256>>>(qmu, qls, pmu, eps, pls);
    kl_reduce_kernel<<<1, 256>>>(out, (long long)out_size - 1);

    cudaFuncSetAttribute(gemm_kernel, cudaFuncAttributeMaxDynamicSharedMemorySize, SMEM_TOTAL);
    gemm_kernel<<<(M_BATCH / BM) * (N_OUT / BN), 256, SMEM_TOTAL>>>(x, out);
}

// round 4
// speedup vs baseline: 1.2539x; 1.0018x over previous
#include <cuda_runtime.h>
#include <cstdint>

#define M_BATCH 8192
#define N_OUT   4096
#define K_IN    4096

// Scratch (device globals: allocation-free per harness rules)
__device__ float g_W[(size_t)N_OUT * K_IN];   // tf32-rounded sampled weights, row-major (n,k)
__device__ float g_bias[N_OUT];               // sampled bias column
__device__ float g_klpart[1024];              // per-block KL partials

__device__ __forceinline__ uint32_t f2tf32(float f) {
    uint32_t u;
    asm("cvt.rna.tf32.f32 %0, %1;" : "=r"(u) : "f"(f));
    return u;
}

// ---------------------------------------------------------------------------
// Prep: W = q_mu + exp(q_ls)*eps -> g_W (tf32-rounded) / g_bias, KL partials
// ---------------------------------------------------------------------------
__global__ __launch_bounds__(256) void prep_kernel(const float* __restrict__ qmu,
                                                   const float* __restrict__ qls,
                                                   const float* __restrict__ pmu,
                                                   const float* __restrict__ eps,
                                                   const float* __restrict__ plsp) {
    const float pls  = *plsp;
    const float inv2 = 0.5f * __expf(-2.0f * pls);
    float kl = 0.f;
    const int NT4 = (N_OUT * (K_IN + 1)) >> 2;
    for (int i4 = blockIdx.x * 256 + threadIdx.x; i4 < NT4; i4 += 1024 * 256) {
        float4 qm = ((const float4*)qmu)[i4];
        float4 ql = ((const float4*)qls)[i4];
        float4 pm = ((const float4*)pmu)[i4];
        float4 ep = ((const float4*)eps)[i4];
        #pragma unroll
        for (int j = 0; j < 4; j++) {
            float qmj = (&qm.x)[j], qlj = (&ql.x)[j];
            float pmj = (&pm.x)[j], epj = (&ep.x)[j];
            float qs = __expf(qlj);
            float w  = fmaf(qs, epj, qmj);
            int e = i4 * 4 + j;
            int n = e / 4097;
            int k = e - n * 4097;
            if (k < K_IN) g_W[(size_t)n * K_IN + k] = __uint_as_float(f2tf32(w));
            else          g_bias[n] = w;
            float d = pmj - qmj;
            kl += (pls - qlj) + fmaf(qs, qs, d * d) * inv2 - 0.5f;
        }
    }
    __shared__ float red[256];
    red[threadIdx.x] = kl;
    __syncthreads();
    #pragma unroll
    for (int s = 128; s > 0; s >>= 1) {
        if (threadIdx.x < s) red[threadIdx.x] += red[threadIdx.x + s];
        __syncthreads();
    }
    if (threadIdx.x == 0) g_klpart[blockIdx.x] = red[0];
}

__global__ void kl_reduce_kernel(float* __restrict__ out, long long idx) {
    float local = 0.f;
    for (int i = threadIdx.x; i < 1024; i += 256) local += g_klpart[i];
    __shared__ float red[256];
    red[threadIdx.x] = local;
    __syncthreads();
    #pragma unroll
    for (int s = 128; s > 0; s >>= 1) {
        if (threadIdx.x < s) red[threadIdx.x] += red[threadIdx.x + s];
        __syncthreads();
    }
    if (threadIdx.x == 0) out[idx] = red[0];
}

// ---------------------------------------------------------------------------
// tf32 mma.sync GEMM: out[m][n] = sum_k X[m][k]*W[n][k] + bias[n]
// CTA 128x256x32, 8 warps (2Mx4N), warp tile 64x64.
// ldmatrix.x4.b16 fragment loads on XOR-swizzled 128B rows,
// register double-buffered (LDSM of kbi+1 overlaps MMA of kbi).
// 4-stage cp.async pipeline.
// ---------------------------------------------------------------------------
#define BM 128
#define BN 256
#define BK 32                          // floats = 128 bytes per row
#define NSTAGE 4
#define A_BYTES (BM * 128)             // 16384
#define STG_BYTES ((BM + BN) * 128)    // 49152
#define SMEM_TOTAL (NSTAGE * STG_BYTES)

__device__ __forceinline__ void cpa16(uint32_t daddr, const float* src) {
    asm volatile("cp.async.cg.shared.global [%0], [%1], 16;" :: "r"(daddr), "l"(src));
}

__device__ __forceinline__ void ldsm4(uint32_t* r, uint32_t addr) {
    asm volatile("ldmatrix.sync.aligned.m8n8.x4.shared.b16 {%0,%1,%2,%3}, [%4];"
                 : "=r"(r[0]), "=r"(r[1]), "=r"(r[2]), "=r"(r[3]) : "r"(addr));
}

__device__ __forceinline__ void mma8(float* c, const uint32_t* a, uint32_t b0, uint32_t b1) {
    asm volatile(
        "mma.sync.aligned.m16n8k8.row.col.f32.tf32.tf32.f32 "
        "{%0,%1,%2,%3}, {%4,%5,%6,%7}, {%8,%9}, {%0,%1,%2,%3};\n"
        : "+f"(c[0]), "+f"(c[1]), "+f"(c[2]), "+f"(c[3])
        : "r"(a[0]), "r"(a[1]), "r"(a[2]), "r"(a[3]), "r"(b0), "r"(b1));
}

__global__ __launch_bounds__(256, 1) void gemm_kernel(const float* __restrict__ X,
                                                      float* __restrict__ out) {
    extern __shared__ char smem[];
    uint32_t sbase;
    asm("{ .reg .u64 t; cvta.to.shared.u64 t, %1; cvt.u32.u64 %0, t; }"
        : "=r"(sbase) : "l"(smem));
    const int tid  = threadIdx.x;
    const int wid  = tid >> 5;
    const int lane = tid & 31;

    // GROUP_M=8 schedule: 64 M-tiles x 16 N-tiles
    const int pid   = blockIdx.x;
    const int group = pid >> 7;
    const int rem   = pid & 127;
    const int blockM = ((group << 3) + (rem & 7)) * BM;
    const int blockN = (rem >> 3) * BN;

    // ---- loader mapping ----
    const int q  = tid & 7;
    const int r0 = tid >> 3;                          // 0..31
    const float* gA = X   + (size_t)(blockM + r0) * K_IN + q * 4;
    const float* gB = g_W + (size_t)(blockN + r0) * K_IN + q * 4;
    const uint32_t soA = r0 * 128 + ((q ^ (r0 & 7)) << 4);
    const uint32_t soB = A_BYTES + soA;

    // ---- fragment geometry ----
    const int mBase = (wid & 1) * 64;                 // 2 M-warps
    const int nBase = (wid >> 1) * 64;                // 4 N-warps
    const uint32_t rl = lane & 7;
    const uint32_t aKbAdd = (lane >> 4) & 1;          // A: matrices 2,3 -> kb+1
    const uint32_t bKbAdd = (lane >> 3) & 1;          // B: matrices 1,3 -> kb+1
    uint32_t aRowOff[4], bRowOff[4];
    #pragma unroll
    for (int i = 0; i < 4; i++)
        aRowOff[i] = (mBase + i * 16 + (lane & 7) + 8 * ((lane >> 3) & 1)) * 128;
    #pragma unroll
    for (int j2 = 0; j2 < 4; j2++)
        bRowOff[j2] = A_BYTES + (nBase + j2 * 16 + (lane & 7) + 8 * ((lane >> 4) & 1)) * 128;

    float acc[4][8][4];
    #pragma unroll
    for (int i = 0; i < 4; i++)
        #pragma unroll
        for (int j = 0; j < 8; j++)
            #pragma unroll
            for (int r = 0; r < 4; r++) acc[i][j][r] = 0.f;

    const int KT = K_IN / BK;                          // 128

    // prologue: stages 0..2
    #pragma unroll
    for (int t = 0; t < 3; t++) {
        uint32_t base = sbase + t * STG_BYTES;
        #pragma unroll
        for (int i = 0; i < 4; i++) cpa16(base + soA + i * 4096, gA + (size_t)t * BK + (size_t)i * 32 * K_IN);
        #pragma unroll
        for (int i = 0; i < 8; i++) cpa16(base + soB + i * 4096, gB + (size_t)t * BK + (size_t)i * 32 * K_IN);
        asm volatile("cp.async.commit_group;");
    }

    uint32_t af[2][4][4], bq[2][4][4];

    for (int t = 0; t < KT; t++) {
        asm volatile("cp.async.wait_group 2;");
        __syncthreads();

        if (t + 3 < KT) {
            uint32_t base = sbase + ((t + 3) & 3) * STG_BYTES;
            const float* ga = gA + (size_t)(t + 3) * BK;
            const float* gb = gB + (size_t)(t + 3) * BK;
            #pragma unroll
            for (int i = 0; i < 4; i++) cpa16(base + soA + i * 4096, ga + (size_t)i * 32 * K_IN);
            #pragma unroll
            for (int i = 0; i < 8; i++) cpa16(base + soB + i * 4096, gb + (size_t)i * 32 * K_IN);
        }
        asm volatile("cp.async.commit_group;");

        const uint32_t stage = sbase + (t & 3) * STG_BYTES;

        // prefetch fragments for kbi-pair 0
        {
            const uint32_t aXor = ((0 + aKbAdd) ^ rl) << 4;
            const uint32_t bXor = ((0 + bKbAdd) ^ rl) << 4;
            #pragma unroll
            for (int i = 0; i < 4; i++) ldsm4(af[0][i], stage + aRowOff[i] + aXor);
            #pragma unroll
            for (int j2 = 0; j2 < 4; j2++) ldsm4(bq[0][j2], stage + bRowOff[j2] + bXor);
        }

        #pragma unroll
        for (int u = 0; u < 4; u++) {                  // kbi = 2u
            const int cur = u & 1, nxt = cur ^ 1;
            if (u < 3) {
                const uint32_t kb2 = 2 * (u + 1);
                const uint32_t aXor = ((kb2 + aKbAdd) ^ rl) << 4;
                const uint32_t bXor = ((kb2 + bKbAdd) ^ rl) << 4;
                #pragma unroll
                for (int i = 0; i < 4; i++) ldsm4(af[nxt][i], stage + aRowOff[i] + aXor);
                #pragma unroll
                for (int j2 = 0; j2 < 4; j2++) ldsm4(bq[nxt][j2], stage + bRowOff[j2] + bXor);
            }
            #pragma unroll
            for (int i = 0; i < 4; i++)
                #pragma unroll
                for (int j2 = 0; j2 < 4; j2++) {
                    mma8(acc[i][2 * j2],     af[cur][i], bq[cur][j2][0], bq[cur][j2][1]);
                    mma8(acc[i][2 * j2 + 1], af[cur][i], bq[cur][j2][2], bq[cur][j2][3]);
                }
        }
    }

    // ---- epilogue: bias add + fp32 stores ----
    const int ly = lane >> 2, lx = lane & 3;
    float2 bias2[8];
    #pragma unroll
    for (int j = 0; j < 8; j++)
        bias2[j] = *(const float2*)&g_bias[blockN + nBase + j * 8 + lx * 2];
    #pragma unroll
    for (int i = 0; i < 4; i++) {
        const int row0 = blockM + mBase + i * 16 + ly;
        #pragma unroll
        for (int j = 0; j < 8; j++) {
            const int col = blockN + nBase + j * 8 + lx * 2;
            float2 v0 = make_float2(acc[i][j][0] + bias2[j].x, acc[i][j][1] + bias2[j].y);
            float2 v1 = make_float2(acc[i][j][2] + bias2[j].x, acc[i][j][3] + bias2[j].y);
            *(float2*)&out[(size_t)row0 * N_OUT + col] = v0;
            *(float2*)&out[(size_t)(row0 + 8) * N_OUT + col] = v1;
        }
    }
}

// ---------------------------------------------------------------------------
extern "C" void kernel_launch(void* const* d_in, const int* in_sizes, int n_in,
                              void* d_out, int out_size) {
    const float* x   = (const float*)d_in[0];
    const float* pls = (const float*)d_in[1];
    const float* qmu = (const float*)d_in[2];
    const float* qls = (const float*)d_in[3];
    const float* pmu = (const float*)d_in[4];
    const float* eps = (const float*)d_in[5];
    float* out = (float*)d_out;

    prep_kernel<<<1024, 256>>>(qmu, qls, pmu, eps, pls);
    kl_reduce_kernel<<<1, 256>>>(out, (long long)out_size - 1);

    cudaFuncSetAttribute(gemm_kernel, cudaFuncAttributeMaxDynamicSharedMemorySize, SMEM_TOTAL);
    gemm_kernel<<<(M_BATCH / BM) * (N_OUT / BN), 256, SMEM_TOTAL>>>(x, out);
}

// round 5
// speedup vs baseline: 2.2830x; 1.8208x over previous
#include <cuda_runtime.h>
#include <cuda_fp16.h>
#include <cstdint>

#define M_BATCH 8192
#define N_OUT   4096
#define K_IN    4096

// Scratch (device globals: allocation-free per harness rules)
__device__ __half g_Wh[(size_t)N_OUT * K_IN];    // fp16 sampled weights (n,k)
__device__ __half g_Xh[(size_t)M_BATCH * K_IN];  // fp16 copy of x
__device__ float  g_bias[N_OUT];                 // sampled bias column
__device__ float  g_klpart[1024];                // per-block KL partials

// ---------------------------------------------------------------------------
// Prep: W = q_mu + exp(q_ls)*eps -> g_Wh (fp16 rn) / g_bias, KL partials
// ---------------------------------------------------------------------------
__global__ __launch_bounds__(256) void prep_kernel(const float* __restrict__ qmu,
                                                   const float* __restrict__ qls,
                                                   const float* __restrict__ pmu,
                                                   const float* __restrict__ eps,
                                                   const float* __restrict__ plsp) {
    const float pls  = *plsp;
    const float inv2 = 0.5f * __expf(-2.0f * pls);
    float kl = 0.f;
    const int NT4 = (N_OUT * (K_IN + 1)) >> 2;
    for (int i4 = blockIdx.x * 256 + threadIdx.x; i4 < NT4; i4 += 1024 * 256) {
        float4 qm = ((const float4*)qmu)[i4];
        float4 ql = ((const float4*)qls)[i4];
        float4 pm = ((const float4*)pmu)[i4];
        float4 ep = ((const float4*)eps)[i4];
        #pragma unroll
        for (int j = 0; j < 4; j++) {
            float qmj = (&qm.x)[j], qlj = (&ql.x)[j];
            float pmj = (&pm.x)[j], epj = (&ep.x)[j];
            float qs = __expf(qlj);
            float w  = fmaf(qs, epj, qmj);
            int e = i4 * 4 + j;
            int n = e / 4097;
            int k = e - n * 4097;
            if (k < K_IN) g_Wh[(size_t)n * K_IN + k] = __float2half_rn(w);
            else          g_bias[n] = w;
            float d = pmj - qmj;
            kl += (pls - qlj) + fmaf(qs, qs, d * d) * inv2 - 0.5f;
        }
    }
    __shared__ float red[256];
    red[threadIdx.x] = kl;
    __syncthreads();
    #pragma unroll
    for (int s = 128; s > 0; s >>= 1) {
        if (threadIdx.x < s) red[threadIdx.x] += red[threadIdx.x + s];
        __syncthreads();
    }
    if (threadIdx.x == 0) g_klpart[blockIdx.x] = red[0];
}

__global__ void kl_reduce_kernel(float* __restrict__ out, long long idx) {
    float local = 0.f;
    for (int i = threadIdx.x; i < 1024; i += 256) local += g_klpart[i];
    __shared__ float red[256];
    red[threadIdx.x] = local;
    __syncthreads();
    #pragma unroll
    for (int s = 128; s > 0; s >>= 1) {
        if (threadIdx.x < s) red[threadIdx.x] += red[threadIdx.x + s];
        __syncthreads();
    }
    if (threadIdx.x == 0) out[idx] = red[0];
}

// ---------------------------------------------------------------------------
// X -> fp16 convert (8 elems / thread, 16B stores)
// ---------------------------------------------------------------------------
__global__ __launch_bounds__(256) void xconv_kernel(const float* __restrict__ X) {
    const int NT8 = (M_BATCH * K_IN) >> 3;   // 4,194,304
    for (int i = blockIdx.x * 256 + threadIdx.x; i < NT8; i += gridDim.x * 256) {
        float4 a = ((const float4*)X)[2 * i];
        float4 b = ((const float4*)X)[2 * i + 1];
        __half2 h[4];
        h[0] = __floats2half2_rn(a.x, a.y);
        h[1] = __floats2half2_rn(a.z, a.w);
        h[2] = __floats2half2_rn(b.x, b.y);
        h[3] = __floats2half2_rn(b.z, b.w);
        ((uint4*)g_Xh)[i] = *(uint4*)h;
    }
}

// ---------------------------------------------------------------------------
// fp16 mma.sync GEMM: out[m][n] = sum_k X[m][k]*W[n][k] + bias[n]
// CTA 128x256x64(halfs), 8 warps (2Mx4N), warp tile 64x64.
// ldmatrix.x4.b16 on XOR-swizzled 128B rows, m16n8k16.f16 mma, f32 acc.
// 4-stage cp.async pipeline.
// ---------------------------------------------------------------------------
#define BM 128
#define BN 256
#define BK 64                          // halfs = 128 bytes per row
#define NSTAGE 4
#define A_BYTES (BM * 128)             // 16384
#define STG_BYTES ((BM + BN) * 128)    // 49152
#define SMEM_TOTAL (NSTAGE * STG_BYTES)

__device__ __forceinline__ void cpa16(uint32_t daddr, const void* src) {
    asm volatile("cp.async.cg.shared.global [%0], [%1], 16;" :: "r"(daddr), "l"(src));
}

__device__ __forceinline__ void ldsm4(uint32_t* r, uint32_t addr) {
    asm volatile("ldmatrix.sync.aligned.m8n8.x4.shared.b16 {%0,%1,%2,%3}, [%4];"
                 : "=r"(r[0]), "=r"(r[1]), "=r"(r[2]), "=r"(r[3]) : "r"(addr));
}

__device__ __forceinline__ void mma16(float* c, const uint32_t* a, uint32_t b0, uint32_t b1) {
    asm volatile(
        "mma.sync.aligned.m16n8k16.row.col.f32.f16.f16.f32 "
        "{%0,%1,%2,%3}, {%4,%5,%6,%7}, {%8,%9}, {%0,%1,%2,%3};\n"
        : "+f"(c[0]), "+f"(c[1]), "+f"(c[2]), "+f"(c[3])
        : "r"(a[0]), "r"(a[1]), "r"(a[2]), "r"(a[3]), "r"(b0), "r"(b1));
}

__global__ __launch_bounds__(256, 1) void gemm_kernel(float* __restrict__ out) {
    extern __shared__ char smem[];
    uint32_t sbase;
    asm("{ .reg .u64 t; cvta.to.shared.u64 t, %1; cvt.u32.u64 %0, t; }"
        : "=r"(sbase) : "l"(smem));
    const int tid  = threadIdx.x;
    const int wid  = tid >> 5;
    const int lane = tid & 31;

    // GROUP_M=8 schedule: 64 M-tiles x 16 N-tiles
    const int pid   = blockIdx.x;
    const int group = pid >> 7;
    const int rem   = pid & 127;
    const int blockM = ((group << 3) + (rem & 7)) * BM;
    const int blockN = (rem >> 3) * BN;

    // ---- loader mapping: q = 16B chunk (8 halfs), rows strided by 32 ----
    const int q  = tid & 7;
    const int r0 = tid >> 3;                          // 0..31
    const __half* gA = g_Xh + (size_t)(blockM + r0) * K_IN + q * 8;
    const __half* gB = g_Wh + (size_t)(blockN + r0) * K_IN + q * 8;
    const uint32_t soA = r0 * 128 + ((q ^ (r0 & 7)) << 4);
    const uint32_t soB = A_BYTES + soA;

    // ---- fragment geometry (fp16 m16n8k16 native ldmatrix mapping) ----
    const int mBase = (wid & 1) * 64;                 // 2 M-warps
    const int nBase = (wid >> 1) * 64;                // 4 N-warps
    const uint32_t rl = lane & 7;
    const uint32_t aKbAdd = (lane >> 4) & 1;          // A: second 16B of k16
    const uint32_t bKbAdd = (lane >> 3) & 1;          // B: second 16B of k16
    uint32_t aRowOff[4], bRowOff[4];
    #pragma unroll
    for (int i = 0; i < 4; i++)
        aRowOff[i] = (mBase + i * 16 + (lane & 7) + 8 * ((lane >> 3) & 1)) * 128;
    #pragma unroll
    for (int j2 = 0; j2 < 4; j2++)
        bRowOff[j2] = A_BYTES + (nBase + j2 * 16 + (lane & 7) + 8 * ((lane >> 4) & 1)) * 128;

    float acc[4][8][4];
    #pragma unroll
    for (int i = 0; i < 4; i++)
        #pragma unroll
        for (int j = 0; j < 8; j++)
            #pragma unroll
            for (int r = 0; r < 4; r++) acc[i][j][r] = 0.f;

    const int KT = K_IN / BK;                          // 64

    // prologue: stages 0..2
    #pragma unroll
    for (int t = 0; t < 3; t++) {
        uint32_t base = sbase + t * STG_BYTES;
        #pragma unroll
        for (int i = 0; i < 4; i++) cpa16(base + soA + i * 4096, gA + (size_t)t * BK + (size_t)i * 32 * K_IN);
        #pragma unroll
        for (int i = 0; i < 8; i++) cpa16(base + soB + i * 4096, gB + (size_t)t * BK + (size_t)i * 32 * K_IN);
        asm volatile("cp.async.commit_group;");
    }

    for (int t = 0; t < KT; t++) {
        asm volatile("cp.async.wait_group 2;");
        __syncthreads();

        if (t + 3 < KT) {
            uint32_t base = sbase + ((t + 3) & 3) * STG_BYTES;
            const __half* ga = gA + (size_t)(t + 3) * BK;
            const __half* gb = gB + (size_t)(t + 3) * BK;
            #pragma unroll
            for (int i = 0; i < 4; i++) cpa16(base + soA + i * 4096, ga + (size_t)i * 32 * K_IN);
            #pragma unroll
            for (int i = 0; i < 8; i++) cpa16(base + soB + i * 4096, gb + (size_t)i * 32 * K_IN);
        }
        asm volatile("cp.async.commit_group;");

        const uint32_t stage = sbase + (t & 3) * STG_BYTES;
        #pragma unroll
        for (int c = 0; c < 4; c++) {                  // 4 x k16 = BK
            const uint32_t aXor = ((2 * c + aKbAdd) ^ rl) << 4;
            const uint32_t bXor = ((2 * c + bKbAdd) ^ rl) << 4;
            uint32_t af[4][4], bq[4][4];
            #pragma unroll
            for (int i = 0; i < 4; i++) ldsm4(af[i], stage + aRowOff[i] + aXor);
            #pragma unroll
            for (int j2 = 0; j2 < 4; j2++) ldsm4(bq[j2], stage + bRowOff[j2] + bXor);
            #pragma unroll
            for (int i = 0; i < 4; i++)
                #pragma unroll
                for (int j2 = 0; j2 < 4; j2++) {
                    mma16(acc[i][2 * j2],     af[i], bq[j2][0], bq[j2][1]);
                    mma16(acc[i][2 * j2 + 1], af[i], bq[j2][2], bq[j2][3]);
                }
        }
    }

    // ---- epilogue: bias add + fp32 stores ----
    const int ly = lane >> 2, lx = lane & 3;
    float2 bias2[8];
    #pragma unroll
    for (int j = 0; j < 8; j++)
        bias2[j] = *(const float2*)&g_bias[blockN + nBase + j * 8 + lx * 2];
    #pragma unroll
    for (int i = 0; i < 4; i++) {
        const int row0 = blockM + mBase + i * 16 + ly;
        #pragma unroll
        for (int j = 0; j < 8; j++) {
            const int col = blockN + nBase + j * 8 + lx * 2;
            float2 v0 = make_float2(acc[i][j][0] + bias2[j].x, acc[i][j][1] + bias2[j].y);
            float2 v1 = make_float2(acc[i][j][2] + bias2[j].x, acc[i][j][3] + bias2[j].y);
            *(float2*)&out[(size_t)row0 * N_OUT + col] = v0;
            *(float2*)&out[(size_t)(row0 + 8) * N_OUT + col] = v1;
        }
    }
}

// ---------------------------------------------------------------------------
extern "C" void kernel_launch(void* const* d_in, const int* in_sizes, int n_in,
                              void* d_out, int out_size) {
    const float* x   = (const float*)d_in[0];
    const float* pls = (const float*)d_in[1];
    const float* qmu = (const float*)d_in[2];
    const float* qls = (const float*)d_in[3];
    const float* pmu = (const float*)d_in[4];
    const float* eps = (const float*)d_in[5];
    float* out = (float*)d_out;

    prep_kernel<<<1024, 256>>>(qmu, qls, pmu, eps, pls);
    xconv_kernel<<<2048, 256>>>(x);
    kl_reduce_kernel<<<1, 256>>>(out, (long long)out_size - 1);

    cudaFuncSetAttribute(gemm_kernel, cudaFuncAttributeMaxDynamicSharedMemorySize, SMEM_TOTAL);
    gemm_kernel<<<(M_BATCH / BM) * (N_OUT / BN), 256, SMEM_TOTAL>>>(out);
}

// round 6
// speedup vs baseline: 2.4889x; 1.0902x over previous
#include <cuda_runtime.h>
#include <cuda_fp16.h>
#include <cstdint>

#define M_BATCH 8192
#define N_OUT   4096
#define K_IN    4096

// Scratch (device globals: allocation-free per harness rules)
__device__ __half g_Wh[(size_t)N_OUT * K_IN];    // fp16 sampled weights (n,k)
__device__ __half g_Xh[(size_t)M_BATCH * K_IN];  // fp16 copy of x
__device__ float  g_bias[N_OUT];                 // sampled bias column
__device__ float  g_klpart[1024];                // per-block KL partials

// ---------------------------------------------------------------------------
// Prep: W = q_mu + exp(q_ls)*eps -> g_Wh (fp16 rn) / g_bias, KL partials
// ---------------------------------------------------------------------------
__global__ __launch_bounds__(256) void prep_kernel(const float* __restrict__ qmu,
                                                   const float* __restrict__ qls,
                                                   const float* __restrict__ pmu,
                                                   const float* __restrict__ eps,
                                                   const float* __restrict__ plsp) {
    const float pls  = *plsp;
    const float inv2 = 0.5f * __expf(-2.0f * pls);
    float kl = 0.f;
    const int NT4 = (N_OUT * (K_IN + 1)) >> 2;
    for (int i4 = blockIdx.x * 256 + threadIdx.x; i4 < NT4; i4 += 1024 * 256) {
        float4 qm = ((const float4*)qmu)[i4];
        float4 ql = ((const float4*)qls)[i4];
        float4 pm = ((const float4*)pmu)[i4];
        float4 ep = ((const float4*)eps)[i4];
        #pragma unroll
        for (int j = 0; j < 4; j++) {
            float qmj = (&qm.x)[j], qlj = (&ql.x)[j];
            float pmj = (&pm.x)[j], epj = (&ep.x)[j];
            float qs = __expf(qlj);
            float w  = fmaf(qs, epj, qmj);
            int e = i4 * 4 + j;
            int n = e / 4097;
            int k = e - n * 4097;
            if (k < K_IN) g_Wh[(size_t)n * K_IN + k] = __float2half_rn(w);
            else          g_bias[n] = w;
            float d = pmj - qmj;
            kl += (pls - qlj) + fmaf(qs, qs, d * d) * inv2 - 0.5f;
        }
    }
    __shared__ float red[256];
    red[threadIdx.x] = kl;
    __syncthreads();
    #pragma unroll
    for (int s = 128; s > 0; s >>= 1) {
        if (threadIdx.x < s) red[threadIdx.x] += red[threadIdx.x + s];
        __syncthreads();
    }
    if (threadIdx.x == 0) g_klpart[blockIdx.x] = red[0];
}

__global__ void kl_reduce_kernel(float* __restrict__ out, long long idx) {
    float local = 0.f;
    for (int i = threadIdx.x; i < 1024; i += 256) local += g_klpart[i];
    __shared__ float red[256];
    red[threadIdx.x] = local;
    __syncthreads();
    #pragma unroll
    for (int s = 128; s > 0; s >>= 1) {
        if (threadIdx.x < s) red[threadIdx.x] += red[threadIdx.x + s];
        __syncthreads();
    }
    if (threadIdx.x == 0) out[idx] = red[0];
}

// ---------------------------------------------------------------------------
// X -> fp16 convert (8 elems / thread, 16B stores)
// ---------------------------------------------------------------------------
__global__ __launch_bounds__(256) void xconv_kernel(const float* __restrict__ X) {
    const int NT8 = (M_BATCH * K_IN) >> 3;
    for (int i = blockIdx.x * 256 + threadIdx.x; i < NT8; i += gridDim.x * 256) {
        float4 a = ((const float4*)X)[2 * i];
        float4 b = ((const float4*)X)[2 * i + 1];
        __half2 h[4];
        h[0] = __floats2half2_rn(a.x, a.y);
        h[1] = __floats2half2_rn(a.z, a.w);
        h[2] = __floats2half2_rn(b.x, b.y);
        h[3] = __floats2half2_rn(b.z, b.w);
        ((uint4*)g_Xh)[i] = *(uint4*)h;
    }
}

// ---------------------------------------------------------------------------
// fp16 mma.sync GEMM: out[m][n] = sum_k X[m][k]*W[n][k] + bias[n]
// CTA 128x128x64(halfs), 8 warps (2Mx4N), warp tile 64x32, 2 CTAs/SM.
// ldmatrix.x4.b16 on XOR-swizzled 128B rows, m16n8k16.f16, f32 acc.
// 3-stage cp.async pipeline (96 KB smem/CTA).
// ---------------------------------------------------------------------------
#define BM 128
#define BN 128
#define BK 64                          // halfs = 128 bytes per row
#define NSTAGE 3
#define A_BYTES (BM * 128)             // 16384
#define STG_BYTES ((BM + BN) * 128)    // 32768
#define SMEM_TOTAL (NSTAGE * STG_BYTES)

__device__ __forceinline__ void cpa16(uint32_t daddr, const void* src) {
    asm volatile("cp.async.cg.shared.global [%0], [%1], 16;" :: "r"(daddr), "l"(src));
}

__device__ __forceinline__ void ldsm4(uint32_t* r, uint32_t addr) {
    asm volatile("ldmatrix.sync.aligned.m8n8.x4.shared.b16 {%0,%1,%2,%3}, [%4];"
                 : "=r"(r[0]), "=r"(r[1]), "=r"(r[2]), "=r"(r[3]) : "r"(addr));
}

__device__ __forceinline__ void mma16(float* c, const uint32_t* a, uint32_t b0, uint32_t b1) {
    asm volatile(
        "mma.sync.aligned.m16n8k16.row.col.f32.f16.f16.f32 "
        "{%0,%1,%2,%3}, {%4,%5,%6,%7}, {%8,%9}, {%0,%1,%2,%3};\n"
        : "+f"(c[0]), "+f"(c[1]), "+f"(c[2]), "+f"(c[3])
        : "r"(a[0]), "r"(a[1]), "r"(a[2]), "r"(a[3]), "r"(b0), "r"(b1));
}

__global__ __launch_bounds__(256, 2) void gemm_kernel(float* __restrict__ out) {
    extern __shared__ char smem[];
    uint32_t sbase;
    asm("{ .reg .u64 t; cvta.to.shared.u64 t, %1; cvt.u32.u64 %0, t; }"
        : "=r"(sbase) : "l"(smem));
    const int tid  = threadIdx.x;
    const int wid  = tid >> 5;
    const int lane = tid & 31;

    // GROUP_M=16 schedule: 64 M-tiles x 32 N-tiles
    const int pid   = blockIdx.x;
    const int group = pid >> 9;                       // / (16*32)
    const int rem   = pid & 511;
    const int blockM = ((group << 4) + (rem & 15)) * BM;
    const int blockN = (rem >> 4) * BN;

    // ---- loader mapping: q = 16B chunk (8 halfs), rows strided by 32 ----
    const int q  = tid & 7;
    const int r0 = tid >> 3;                          // 0..31
    const __half* gA = g_Xh + (size_t)(blockM + r0) * K_IN + q * 8;
    const __half* gB = g_Wh + (size_t)(blockN + r0) * K_IN + q * 8;
    const uint32_t soA = r0 * 128 + ((q ^ (r0 & 7)) << 4);
    const uint32_t soB = A_BYTES + soA;

    // ---- fragment geometry ----
    const int mBase = (wid & 1) * 64;                 // 2 M-warps
    const int nBase = (wid >> 1) * 32;                // 4 N-warps x 32
    const uint32_t rl = lane & 7;
    const uint32_t aKbAdd = (lane >> 4) & 1;
    const uint32_t bKbAdd = (lane >> 3) & 1;
    uint32_t aRowOff[4], bRowOff[2];
    #pragma unroll
    for (int i = 0; i < 4; i++)
        aRowOff[i] = (mBase + i * 16 + (lane & 7) + 8 * ((lane >> 3) & 1)) * 128;
    #pragma unroll
    for (int j2 = 0; j2 < 2; j2++)
        bRowOff[j2] = A_BYTES + (nBase + j2 * 16 + (lane & 7) + 8 * ((lane >> 4) & 1)) * 128;

    float acc[4][4][4];
    #pragma unroll
    for (int i = 0; i < 4; i++)
        #pragma unroll
        for (int j = 0; j < 4; j++)
            #pragma unroll
            for (int r = 0; r < 4; r++) acc[i][j][r] = 0.f;

    const int KT = K_IN / BK;                          // 64

    // prologue: stages 0,1
    #pragma unroll
    for (int t = 0; t < 2; t++) {
        uint32_t base = sbase + t * STG_BYTES;
        #pragma unroll
        for (int i = 0; i < 4; i++) {
            cpa16(base + soA + i * 4096, gA + (size_t)t * BK + (size_t)i * 32 * K_IN);
            cpa16(base + soB + i * 4096, gB + (size_t)t * BK + (size_t)i * 32 * K_IN);
        }
        asm volatile("cp.async.commit_group;");
    }

    int sCur = 0, sNxt = 2;                            // buf indices mod 3
    for (int t = 0; t < KT; t++) {
        asm volatile("cp.async.wait_group 1;");
        __syncthreads();

        if (t + 2 < KT) {
            uint32_t base = sbase + sNxt * STG_BYTES;
            const __half* ga = gA + (size_t)(t + 2) * BK;
            const __half* gb = gB + (size_t)(t + 2) * BK;
            #pragma unroll
            for (int i = 0; i < 4; i++) {
                cpa16(base + soA + i * 4096, ga + (size_t)i * 32 * K_IN);
                cpa16(base + soB + i * 4096, gb + (size_t)i * 32 * K_IN);
            }
        }
        asm volatile("cp.async.commit_group;");

        const uint32_t stage = sbase + sCur * STG_BYTES;
        #pragma unroll
        for (int c = 0; c < 4; c++) {                  // 4 x k16 = BK
            const uint32_t aXor = ((2 * c + aKbAdd) ^ rl) << 4;
            const uint32_t bXor = ((2 * c + bKbAdd) ^ rl) << 4;
            uint32_t af[4][4], bq[2][4];
            #pragma unroll
            for (int i = 0; i < 4; i++) ldsm4(af[i], stage + aRowOff[i] + aXor);
            #pragma unroll
            for (int j2 = 0; j2 < 2; j2++) ldsm4(bq[j2], stage + bRowOff[j2] + bXor);
            #pragma unroll
            for (int i = 0; i < 4; i++)
                #pragma unroll
                for (int j2 = 0; j2 < 2; j2++) {
                    mma16(acc[i][2 * j2],     af[i], bq[j2][0], bq[j2][1]);
                    mma16(acc[i][2 * j2 + 1], af[i], bq[j2][2], bq[j2][3]);
                }
        }
        sCur = sCur == 2 ? 0 : sCur + 1;
        sNxt = sNxt == 2 ? 0 : sNxt + 1;
    }

    // ---- epilogue: bias add + fp32 stores ----
    const int ly = lane >> 2, lx = lane & 3;
    float2 bias2[4];
    #pragma unroll
    for (int j = 0; j < 4; j++)
        bias2[j] = *(const float2*)&g_bias[blockN + nBase + j * 8 + lx * 2];
    #pragma unroll
    for (int i = 0; i < 4; i++) {
        const int row0 = blockM + mBase + i * 16 + ly;
        #pragma unroll
        for (int j = 0; j < 4; j++) {
            const int col = blockN + nBase + j * 8 + lx * 2;
            float2 v0 = make_float2(acc[i][j][0] + bias2[j].x, acc[i][j][1] + bias2[j].y);
            float2 v1 = make_float2(acc[i][j][2] + bias2[j].x, acc[i][j][3] + bias2[j].y);
            *(float2*)&out[(size_t)row0 * N_OUT + col] = v0;
            *(float2*)&out[(size_t)(row0 + 8) * N_OUT + col] = v1;
        }
    }
}

// ---------------------------------------------------------------------------
extern "C" void kernel_launch(void* const* d_in, const int* in_sizes, int n_in,
                              void* d_out, int out_size) {
    const float* x   = (const float*)d_in[0];
    const float* pls = (const float*)d_in[1];
    const float* qmu = (const float*)d_in[2];
    const float* qls = (const float*)d_in[3];
    const float* pmu = (const float*)d_in[4];
    const float* eps = (const float*)d_in[5];
    float* out = (float*)d_out;

    prep_kernel<<<1024, 256>>>(qmu, qls, pmu, eps, pls);
    xconv_kernel<<<2048, 256>>>(x);
    kl_reduce_kernel<<<1, 256>>>(out, (long long)out_size - 1);

    cudaFuncSetAttribute(gemm_kernel, cudaFuncAttributeMaxDynamicSharedMemorySize, SMEM_TOTAL);
    gemm_kernel<<<(M_BATCH / BM) * (N_OUT / BN), 256, SMEM_TOTAL>>>(out);
}